// round 6
// baseline (speedup 1.0000x reference)
#include <cuda_runtime.h>
#include <cuda_bf16.h>
#include <cstdint>

#define BB 4
#define SS 2048
#define EE 1024
#define HH 16
#define DD 64
#define NTILES 32
#define QROWS 128            // q-rows per CTA (4 row-groups x 32)
#define PK 68                // Kt pitch: QK B-frag loads conflict-free
#define PVP 72               // Vs pitch: PV B-frag loads conflict-free
#define PP 68                // Ps pitch: PV A-frag loads conflict-free

static const long long OUT_ELEMS  = (long long)BB * SS * EE;        // 8388608
static const long long ATTN_ELEMS = (long long)BB * HH * SS * SS;   // 268435456

// per-row normalization constant: log2(1 / sum_k exp(q.k/32))
__device__ float g_logc[BB * HH * SS];

__device__ __forceinline__ uint32_t f2tf(float x) {
    uint32_t r;
    asm("cvt.rna.tf32.f32 %0, %1;" : "=r"(r) : "f"(x));
    return r;
}

__device__ __forceinline__ void mma_tf32(float& c0, float& c1, float& c2, float& c3,
                                         uint32_t a0, uint32_t a1, uint32_t a2, uint32_t a3,
                                         uint32_t b0, uint32_t b1)
{
    asm volatile(
        "mma.sync.aligned.m16n8k8.row.col.f32.tf32.tf32.f32 "
        "{%0,%1,%2,%3}, {%4,%5,%6,%7}, {%8,%9}, {%0,%1,%2,%3};"
        : "+f"(c0), "+f"(c1), "+f"(c2), "+f"(c3)
        : "r"(a0), "r"(a1), "r"(a2), "r"(a3), "r"(b0), "r"(b1));
}

#define LOAD_A_FRAGS(A, qg, qr0)                                             \
    _Pragma("unroll")                                                        \
    for (int kb = 0; kb < 8; kb++) {                                         \
        A[kb][0] = f2tf(qg[(size_t)(qr0)        * EE + kb * 8 + tid4]);      \
        A[kb][1] = f2tf(qg[(size_t)((qr0) + 8)  * EE + kb * 8 + tid4]);      \
        A[kb][2] = f2tf(qg[(size_t)(qr0)        * EE + kb * 8 + tid4 + 4]);  \
        A[kb][3] = f2tf(qg[(size_t)((qr0) + 8)  * EE + kb * 8 + tid4 + 4]);  \
        A[kb][4] = f2tf(qg[(size_t)((qr0) + 16) * EE + kb * 8 + tid4]);      \
        A[kb][5] = f2tf(qg[(size_t)((qr0) + 24) * EE + kb * 8 + tid4]);      \
        A[kb][6] = f2tf(qg[(size_t)((qr0) + 16) * EE + kb * 8 + tid4 + 4]);  \
        A[kb][7] = f2tf(qg[(size_t)((qr0) + 24) * EE + kb * 8 + tid4 + 4]);  \
    }

extern __shared__ float smem_dyn[];

// ============ Kernel 1: row sums ============
// 8 warps: warp (wq, wn) = rows [wq*32..+32) x keys [wn*32..+32) of each tile.
__global__ __launch_bounds__(256, 3)
void attn_sums(const float* __restrict__ q, const float* __restrict__ k)
{
    float* Kt  = smem_dyn;                 // [64 keys][PK] tf32-rounded
    float* red = Kt + 64 * PK;             // [128] cross-wn partial sums

    const int b = blockIdx.z, h = blockIdx.y, qt = blockIdx.x;
    const int t = threadIdx.x, w = t >> 5, lane = t & 31;
    const int gid = lane >> 2, tid4 = lane & 3;
    const int wq = w >> 1, wn = w & 1;
    const int nb0 = wn * 32;
    const float cs = 1.4426950408889634f / 32.0f;   // log2(e)/32
    const int qr0 = wq * 32 + gid;

    const float* qg = q + ((size_t)(b * SS + qt * QROWS)) * EE + h * DD;
    uint32_t A[8][8];
    LOAD_A_FRAGS(A, qg, qr0)

    const float* kg0 = k + ((size_t)b * SS) * EE + h * DD;
    float lp[4] = {0.f, 0.f, 0.f, 0.f};

    for (int kt = 0; kt < NTILES; kt++) {
        const float* kg = kg0 + (size_t)kt * 64 * EE;
        for (int i = t; i < 1024; i += 256) {
            int r = i >> 4, c4 = i & 15;
            float4 kv = *(const float4*)(kg + (size_t)r * EE + c4 * 4);
            float4 ko;
            ko.x = __uint_as_float(f2tf(kv.x));
            ko.y = __uint_as_float(f2tf(kv.y));
            ko.z = __uint_as_float(f2tf(kv.z));
            ko.w = __uint_as_float(f2tf(kv.w));
            *(float4*)&Kt[r * PK + c4 * 4] = ko;
        }
        __syncthreads();

#pragma unroll
        for (int nb = 0; nb < 4; nb++) {
            float S[8] = {0.f,0.f,0.f,0.f,0.f,0.f,0.f,0.f};
#pragma unroll
            for (int kb = 0; kb < 8; kb++) {
                uint32_t b0 = __float_as_uint(Kt[(nb0 + nb * 8 + gid) * PK + kb * 8 + tid4]);
                uint32_t b1 = __float_as_uint(Kt[(nb0 + nb * 8 + gid) * PK + kb * 8 + tid4 + 4]);
                mma_tf32(S[0], S[1], S[2], S[3], A[kb][0], A[kb][1], A[kb][2], A[kb][3], b0, b1);
                mma_tf32(S[4], S[5], S[6], S[7], A[kb][4], A[kb][5], A[kb][6], A[kb][7], b0, b1);
            }
            lp[0] += exp2f(S[0] * cs) + exp2f(S[1] * cs);
            lp[1] += exp2f(S[2] * cs) + exp2f(S[3] * cs);
            lp[2] += exp2f(S[4] * cs) + exp2f(S[5] * cs);
            lp[3] += exp2f(S[6] * cs) + exp2f(S[7] * cs);
        }
        __syncthreads();
    }

#pragma unroll
    for (int i = 0; i < 4; i++) {
        lp[i] += __shfl_xor_sync(0xFFFFFFFFu, lp[i], 1);
        lp[i] += __shfl_xor_sync(0xFFFFFFFFu, lp[i], 2);
    }
    if (wn == 1 && tid4 == 0) {
#pragma unroll
        for (int i = 0; i < 4; i++) red[qr0 + 8 * i] = lp[i];
    }
    __syncthreads();
    if (wn == 0 && tid4 == 0) {
        size_t base = (size_t)((b * HH + h) * SS) + (size_t)qt * QROWS;
#pragma unroll
        for (int i = 0; i < 4; i++)
            g_logc[base + qr0 + 8 * i] = -log2f(lp[i] + red[qr0 + 8 * i]);
    }
}

// ============ Kernel 2: normalized attn + O ============
// 8 warps: warp (wq, wn) = rows [wq*32..+32) x keys [wn*32..+32) of each tile.
// Each warp accumulates a partial O over its key-half; cross-wn reduce at end.
__global__ __launch_bounds__(256, 3)
void attn_main(const float* __restrict__ q, const float* __restrict__ k,
               const float* __restrict__ v, float* __restrict__ out,
               float* __restrict__ attn, int write_attn)
{
    float* Kt = smem_dyn;              // [64 keys][PK]
    float* Vs = Kt + 64 * PK;          // [64 keys][PVP]
    float* Ps = Vs + 64 * PVP;         // [128 q][PP] normalized P (+ O reduce buf)

    const int b = blockIdx.z, h = blockIdx.y, qt = blockIdx.x;
    const int t = threadIdx.x, w = t >> 5, lane = t & 31;
    const int gid = lane >> 2, tid4 = lane & 3;
    const int wq = w >> 1, wn = w & 1;
    const int nb0 = wn * 32;
    const float cs = 1.4426950408889634f / 32.0f;
    const int qr0 = wq * 32 + gid;

    const float* qg = q + ((size_t)(b * SS + qt * QROWS)) * EE + h * DD;
    uint32_t A[8][8];
    LOAD_A_FRAGS(A, qg, qr0)

    float c0add, c1add, c2add, c3add;
    {
        size_t base = (size_t)((b * HH + h) * SS) + (size_t)qt * QROWS;
        c0add = g_logc[base + qr0];
        c1add = g_logc[base + qr0 + 8];
        c2add = g_logc[base + qr0 + 16];
        c3add = g_logc[base + qr0 + 24];
    }

    float O0[8][4], O1[8][4];
#pragma unroll
    for (int nb = 0; nb < 8; nb++)
#pragma unroll
        for (int j = 0; j < 4; j++) { O0[nb][j] = 0.f; O1[nb][j] = 0.f; }

    const float* kg0 = k + ((size_t)b * SS) * EE + h * DD;
    const float* vg0 = v + ((size_t)b * SS) * EE + h * DD;
    float* attng = attn + ((size_t)((b * HH + h) * SS) + (size_t)qt * QROWS) * SS;

    for (int kt = 0; kt < NTILES; kt++) {
        const float* kg = kg0 + (size_t)kt * 64 * EE;
        const float* vg = vg0 + (size_t)kt * 64 * EE;
        for (int i = t; i < 1024; i += 256) {
            int r = i >> 4, c4 = i & 15;
            float4 kv = *(const float4*)(kg + (size_t)r * EE + c4 * 4);
            float4 ko;
            ko.x = __uint_as_float(f2tf(kv.x));
            ko.y = __uint_as_float(f2tf(kv.y));
            ko.z = __uint_as_float(f2tf(kv.z));
            ko.w = __uint_as_float(f2tf(kv.w));
            *(float4*)&Kt[r * PK + c4 * 4] = ko;
            float4 vv = *(const float4*)(vg + (size_t)r * EE + c4 * 4);
            float4 vo;
            vo.x = __uint_as_float(f2tf(vv.x));
            vo.y = __uint_as_float(f2tf(vv.y));
            vo.z = __uint_as_float(f2tf(vv.z));
            vo.w = __uint_as_float(f2tf(vv.w));
            *(float4*)&Vs[r * PVP + c4 * 4] = vo;
        }
        __syncthreads();

        // ---- QK (4 nb blocks in this warp's key-half) + normalized exp -> Ps ----
#pragma unroll
        for (int nb = 0; nb < 4; nb++) {
            float S[8] = {0.f,0.f,0.f,0.f,0.f,0.f,0.f,0.f};
#pragma unroll
            for (int kb = 0; kb < 8; kb++) {
                uint32_t b0 = __float_as_uint(Kt[(nb0 + nb * 8 + gid) * PK + kb * 8 + tid4]);
                uint32_t b1 = __float_as_uint(Kt[(nb0 + nb * 8 + gid) * PK + kb * 8 + tid4 + 4]);
                mma_tf32(S[0], S[1], S[2], S[3], A[kb][0], A[kb][1], A[kb][2], A[kb][3], b0, b1);
                mma_tf32(S[4], S[5], S[6], S[7], A[kb][4], A[kb][5], A[kb][6], A[kb][7], b0, b1);
            }
            float p0 = exp2f(fmaf(S[0], cs, c0add));
            float p1 = exp2f(fmaf(S[1], cs, c0add));
            float p2 = exp2f(fmaf(S[2], cs, c1add));
            float p3 = exp2f(fmaf(S[3], cs, c1add));
            float p4 = exp2f(fmaf(S[4], cs, c2add));
            float p5 = exp2f(fmaf(S[5], cs, c2add));
            float p6 = exp2f(fmaf(S[6], cs, c3add));
            float p7 = exp2f(fmaf(S[7], cs, c3add));
            int c = nb0 + nb * 8 + 2 * tid4;
            *(float2*)&Ps[(size_t)qr0        * PP + c] = make_float2(p0, p1);
            *(float2*)&Ps[(size_t)(qr0 + 8)  * PP + c] = make_float2(p2, p3);
            *(float2*)&Ps[(size_t)(qr0 + 16) * PP + c] = make_float2(p4, p5);
            *(float2*)&Ps[(size_t)(qr0 + 24) * PP + c] = make_float2(p6, p7);
        }
        // warp-private Ps block (its rows x its cols): no barrier before PV/store.

        // ---- O += P V over this warp's 32 keys ----
#pragma unroll
        for (int kb = 0; kb < 4; kb++) {
            int kbase = nb0 + kb * 8;
            uint32_t pa0 = f2tf(Ps[(size_t)qr0        * PP + kbase + tid4]);
            uint32_t pa1 = f2tf(Ps[(size_t)(qr0 + 8)  * PP + kbase + tid4]);
            uint32_t pa2 = f2tf(Ps[(size_t)qr0        * PP + kbase + tid4 + 4]);
            uint32_t pa3 = f2tf(Ps[(size_t)(qr0 + 8)  * PP + kbase + tid4 + 4]);
            uint32_t pb0 = f2tf(Ps[(size_t)(qr0 + 16) * PP + kbase + tid4]);
            uint32_t pb1 = f2tf(Ps[(size_t)(qr0 + 24) * PP + kbase + tid4]);
            uint32_t pb2 = f2tf(Ps[(size_t)(qr0 + 16) * PP + kbase + tid4 + 4]);
            uint32_t pb3 = f2tf(Ps[(size_t)(qr0 + 24) * PP + kbase + tid4 + 4]);
#pragma unroll
            for (int nb = 0; nb < 8; nb++) {
                uint32_t b0 = __float_as_uint(Vs[(kbase + tid4)     * PVP + nb * 8 + gid]);
                uint32_t b1 = __float_as_uint(Vs[(kbase + tid4 + 4) * PVP + nb * 8 + gid]);
                mma_tf32(O0[nb][0], O0[nb][1], O0[nb][2], O0[nb][3], pa0, pa1, pa2, pa3, b0, b1);
                mma_tf32(O1[nb][0], O1[nb][1], O1[nb][2], O1[nb][3], pb0, pb1, pb2, pb3, b0, b1);
            }
        }

        // ---- store normalized P (warp's 32 rows x 32 cols, coalesced) ----
        if (write_attn) {
            float* ag = attng + kt * 64 + nb0;
            for (int i = lane; i < 256; i += 32) {
                int r = wq * 32 + (i >> 3), c4 = i & 7;
                *(float4*)(ag + (size_t)r * SS + c4 * 4) =
                    *(const float4*)&Ps[(size_t)r * PP + nb0 + c4 * 4];
            }
        }
        __syncthreads();   // protect Kt/Vs/Ps restage
    }

    // ---- cross-wn O reduction through smem (reuse Ps area), then out ----
    float* Osm = Ps;
    if (wn == 1) {
#pragma unroll
        for (int nb = 0; nb < 8; nb++) {
            int c = nb * 8 + 2 * tid4;
            *(float2*)&Osm[(size_t)qr0        * PP + c] = make_float2(O0[nb][0], O0[nb][1]);
            *(float2*)&Osm[(size_t)(qr0 + 8)  * PP + c] = make_float2(O0[nb][2], O0[nb][3]);
            *(float2*)&Osm[(size_t)(qr0 + 16) * PP + c] = make_float2(O1[nb][0], O1[nb][1]);
            *(float2*)&Osm[(size_t)(qr0 + 24) * PP + c] = make_float2(O1[nb][2], O1[nb][3]);
        }
    }
    __syncthreads();
    if (wn == 0) {
        float* og = out + ((size_t)(b * SS + qt * QROWS)) * EE + h * DD;
#pragma unroll
        for (int nb = 0; nb < 8; nb++) {
            int c = nb * 8 + 2 * tid4;
            float2 a0 = *(const float2*)&Osm[(size_t)qr0        * PP + c];
            float2 a1 = *(const float2*)&Osm[(size_t)(qr0 + 8)  * PP + c];
            float2 a2 = *(const float2*)&Osm[(size_t)(qr0 + 16) * PP + c];
            float2 a3 = *(const float2*)&Osm[(size_t)(qr0 + 24) * PP + c];
            *(float2*)(og + (size_t)qr0        * EE + c) = make_float2(O0[nb][0] + a0.x, O0[nb][1] + a0.y);
            *(float2*)(og + (size_t)(qr0 + 8)  * EE + c) = make_float2(O0[nb][2] + a1.x, O0[nb][3] + a1.y);
            *(float2*)(og + (size_t)(qr0 + 16) * EE + c) = make_float2(O1[nb][0] + a2.x, O1[nb][1] + a2.y);
            *(float2*)(og + (size_t)(qr0 + 24) * EE + c) = make_float2(O1[nb][2] + a3.x, O1[nb][3] + a3.y);
        }
    }
}

static const size_t SHMEM_SUMS = (size_t)(64 * PK + 128) * sizeof(float);                  // 17920
static const size_t SHMEM_MAIN = (size_t)(64 * PK + 64 * PVP + QROWS * PP) * sizeof(float); // 70656

static bool setup_once()
{
    cudaFuncSetAttribute(attn_sums, cudaFuncAttributeMaxDynamicSharedMemorySize,
                         (int)SHMEM_SUMS);
    cudaFuncSetAttribute(attn_main, cudaFuncAttributeMaxDynamicSharedMemorySize,
                         (int)SHMEM_MAIN);
    return true;
}

extern "C" void kernel_launch(void* const* d_in, const int* in_sizes, int n_in,
                              void* d_out, int out_size)
{
    static bool ready = setup_once();
    (void)ready;

    const float* q = (const float*)d_in[0];
    const float* k = (const float*)d_in[1];
    const float* v = (const float*)d_in[2];
    float* out  = (float*)d_out;
    float* attn = out + OUT_ELEMS;

    const long long need = OUT_ELEMS + ATTN_ELEMS;
    const int write_attn = ((long long)out_size >= need) ? 1 : 0;

    dim3 grid(SS / QROWS, HH, BB);
    attn_sums<<<grid, 256, SHMEM_SUMS>>>(q, k);
    attn_main<<<grid, 256, SHMEM_MAIN>>>(q, k, v, out, attn, write_attn);
}

// round 7
// speedup vs baseline: 1.9933x; 1.9933x over previous
#include <cuda_runtime.h>
#include <cuda_bf16.h>
#include <cstdint>

#define BB 4
#define SS 2048
#define EE 1024
#define HH 16
#define DD 64
#define NTILES 32
#define QROWS 64             // q-rows per CTA (4 warps x 16)
#define PK 68                // Kt pitch: QK B-frag loads conflict-free
#define PVP 72               // Vs pitch: PV B-frag loads conflict-free
#define PP 68                // Ps pitch: PV A-frag loads conflict-free

static const long long OUT_ELEMS  = (long long)BB * SS * EE;        // 8388608
static const long long ATTN_ELEMS = (long long)BB * HH * SS * SS;   // 268435456

// per-row normalization constant: log2(1 / sum_k exp(q.k/32))
__device__ float g_logc[BB * HH * SS];

__device__ __forceinline__ uint32_t f2tf(float x) {
    uint32_t r;
    asm("cvt.rna.tf32.f32 %0, %1;" : "=r"(r) : "f"(x));
    return r;
}

__device__ __forceinline__ void mma_tf32(float& c0, float& c1, float& c2, float& c3,
                                         uint32_t a0, uint32_t a1, uint32_t a2, uint32_t a3,
                                         uint32_t b0, uint32_t b1)
{
    asm volatile(
        "mma.sync.aligned.m16n8k8.row.col.f32.tf32.tf32.f32 "
        "{%0,%1,%2,%3}, {%4,%5,%6,%7}, {%8,%9}, {%0,%1,%2,%3};"
        : "+f"(c0), "+f"(c1), "+f"(c2), "+f"(c3)
        : "r"(a0), "r"(a1), "r"(a2), "r"(a3), "r"(b0), "r"(b1));
}

// m16 A fragments: 8 k-blocks x 4 regs = 32 regs
#define LOAD_A16(A, qg, qr0)                                                 \
    _Pragma("unroll")                                                        \
    for (int kb = 0; kb < 8; kb++) {                                         \
        A[kb][0] = f2tf(qg[(size_t)(qr0)       * EE + kb * 8 + tid4]);       \
        A[kb][1] = f2tf(qg[(size_t)((qr0) + 8) * EE + kb * 8 + tid4]);       \
        A[kb][2] = f2tf(qg[(size_t)(qr0)       * EE + kb * 8 + tid4 + 4]);   \
        A[kb][3] = f2tf(qg[(size_t)((qr0) + 8) * EE + kb * 8 + tid4 + 4]);   \
    }

extern __shared__ float smem_dyn[];

// ============ Kernel 1: row sums (QK + exp + reduce only) ============
// CTA = 64 q-rows, 4 warps x m16. High occupancy: ~60 regs, 17.4KB smem.
__global__ __launch_bounds__(128, 6)
void attn_sums(const float* __restrict__ q, const float* __restrict__ k)
{
    float* Kt = smem_dyn;              // [64 keys][PK] tf32-rounded

    const int b = blockIdx.z, h = blockIdx.y, qt = blockIdx.x;
    const int t = threadIdx.x, w = t >> 5, lane = t & 31;
    const int gid = lane >> 2, tid4 = lane & 3;
    const float cs = 1.4426950408889634f / 32.0f;   // log2(e)/32
    const int qr0 = w * 16 + gid;

    const float* qg = q + ((size_t)(b * SS + qt * QROWS)) * EE + h * DD;
    uint32_t A[8][4];
    LOAD_A16(A, qg, qr0)

    const float* kg0 = k + ((size_t)b * SS) * EE + h * DD;
    float lp0 = 0.f, lp1 = 0.f;

    for (int kt = 0; kt < NTILES; kt++) {
        const float* kg = kg0 + (size_t)kt * 64 * EE;
        for (int i = t; i < 1024; i += 128) {
            int r = i >> 4, c4 = i & 15;
            float4 kv = *(const float4*)(kg + (size_t)r * EE + c4 * 4);
            float4 ko;
            ko.x = __uint_as_float(f2tf(kv.x));
            ko.y = __uint_as_float(f2tf(kv.y));
            ko.z = __uint_as_float(f2tf(kv.z));
            ko.w = __uint_as_float(f2tf(kv.w));
            *(float4*)&Kt[r * PK + c4 * 4] = ko;
        }
        __syncthreads();

#pragma unroll
        for (int nb = 0; nb < 8; nb++) {
            float S[4] = {0.f, 0.f, 0.f, 0.f};
#pragma unroll
            for (int kb = 0; kb < 8; kb++) {
                uint32_t b0 = __float_as_uint(Kt[(nb * 8 + gid) * PK + kb * 8 + tid4]);
                uint32_t b1 = __float_as_uint(Kt[(nb * 8 + gid) * PK + kb * 8 + tid4 + 4]);
                mma_tf32(S[0], S[1], S[2], S[3],
                         A[kb][0], A[kb][1], A[kb][2], A[kb][3], b0, b1);
            }
            lp0 += exp2f(S[0] * cs) + exp2f(S[1] * cs);
            lp1 += exp2f(S[2] * cs) + exp2f(S[3] * cs);
        }
        __syncthreads();
    }

    lp0 += __shfl_xor_sync(0xFFFFFFFFu, lp0, 1);
    lp0 += __shfl_xor_sync(0xFFFFFFFFu, lp0, 2);
    lp1 += __shfl_xor_sync(0xFFFFFFFFu, lp1, 1);
    lp1 += __shfl_xor_sync(0xFFFFFFFFu, lp1, 2);
    if (tid4 == 0) {
        size_t base = (size_t)((b * HH + h) * SS) + (size_t)qt * QROWS;
        g_logc[base + qr0]     = -log2f(lp0);
        g_logc[base + qr0 + 8] = -log2f(lp1);
    }
}

// ============ Kernel 2: normalized attn + O ============
// Round-3 pass1 structure (m16, Ps smem), reg-capped at 128 for 4 CTAs/SM.
__global__ __launch_bounds__(128, 4)
void attn_main(const float* __restrict__ q, const float* __restrict__ k,
               const float* __restrict__ v, float* __restrict__ out,
               float* __restrict__ attn, int write_attn)
{
    float* Kt = smem_dyn;              // [64 keys][PK]
    float* Vs = Kt + 64 * PK;          // [64 keys][PVP]
    float* Ps = Vs + 64 * PVP;         // [64 q][PP] normalized P

    const int b = blockIdx.z, h = blockIdx.y, qt = blockIdx.x;
    const int t = threadIdx.x, w = t >> 5, lane = t & 31;
    const int gid = lane >> 2, tid4 = lane & 3;
    const float cs = 1.4426950408889634f / 32.0f;
    const int qr0 = w * 16 + gid;

    const float* qg = q + ((size_t)(b * SS + qt * QROWS)) * EE + h * DD;
    uint32_t A[8][4];
    LOAD_A16(A, qg, qr0)

    float c0add, c1add;
    {
        size_t base = (size_t)((b * HH + h) * SS) + (size_t)qt * QROWS;
        c0add = g_logc[base + qr0];
        c1add = g_logc[base + qr0 + 8];
    }

    float Oacc[8][4];
#pragma unroll
    for (int nb = 0; nb < 8; nb++)
#pragma unroll
        for (int j = 0; j < 4; j++) Oacc[nb][j] = 0.f;

    const float* kg0 = k + ((size_t)b * SS) * EE + h * DD;
    const float* vg0 = v + ((size_t)b * SS) * EE + h * DD;
    float* attng = attn + ((size_t)((b * HH + h) * SS) + (size_t)qt * QROWS) * SS;

    for (int kt = 0; kt < NTILES; kt++) {
        const float* kg = kg0 + (size_t)kt * 64 * EE;
        const float* vg = vg0 + (size_t)kt * 64 * EE;
        for (int i = t; i < 1024; i += 128) {
            int r = i >> 4, c4 = i & 15;
            float4 kv = *(const float4*)(kg + (size_t)r * EE + c4 * 4);
            float4 ko;
            ko.x = __uint_as_float(f2tf(kv.x));
            ko.y = __uint_as_float(f2tf(kv.y));
            ko.z = __uint_as_float(f2tf(kv.z));
            ko.w = __uint_as_float(f2tf(kv.w));
            *(float4*)&Kt[r * PK + c4 * 4] = ko;
            float4 vv = *(const float4*)(vg + (size_t)r * EE + c4 * 4);
            float4 vo;
            vo.x = __uint_as_float(f2tf(vv.x));
            vo.y = __uint_as_float(f2tf(vv.y));
            vo.z = __uint_as_float(f2tf(vv.z));
            vo.w = __uint_as_float(f2tf(vv.w));
            *(float4*)&Vs[r * PVP + c4 * 4] = vo;
        }
        __syncthreads();

        // ---- QK (nb-outer, S transient) + normalized exp -> Ps ----
#pragma unroll
        for (int nb = 0; nb < 8; nb++) {
            float S[4] = {0.f, 0.f, 0.f, 0.f};
#pragma unroll
            for (int kb = 0; kb < 8; kb++) {
                uint32_t b0 = __float_as_uint(Kt[(nb * 8 + gid) * PK + kb * 8 + tid4]);
                uint32_t b1 = __float_as_uint(Kt[(nb * 8 + gid) * PK + kb * 8 + tid4 + 4]);
                mma_tf32(S[0], S[1], S[2], S[3],
                         A[kb][0], A[kb][1], A[kb][2], A[kb][3], b0, b1);
            }
            float p0 = exp2f(fmaf(S[0], cs, c0add));
            float p1 = exp2f(fmaf(S[1], cs, c0add));
            float p2 = exp2f(fmaf(S[2], cs, c1add));
            float p3 = exp2f(fmaf(S[3], cs, c1add));
            *(float2*)&Ps[(size_t)qr0       * PP + nb * 8 + 2 * tid4] = make_float2(p0, p1);
            *(float2*)&Ps[(size_t)(qr0 + 8) * PP + nb * 8 + 2 * tid4] = make_float2(p2, p3);
        }
        // warp-private Ps rows: no barrier needed before PV / attn store.

        // ---- O += P V ----
#pragma unroll
        for (int kb = 0; kb < 8; kb++) {
            uint32_t pa0 = f2tf(Ps[(size_t)qr0       * PP + kb * 8 + tid4]);
            uint32_t pa1 = f2tf(Ps[(size_t)(qr0 + 8) * PP + kb * 8 + tid4]);
            uint32_t pa2 = f2tf(Ps[(size_t)qr0       * PP + kb * 8 + tid4 + 4]);
            uint32_t pa3 = f2tf(Ps[(size_t)(qr0 + 8) * PP + kb * 8 + tid4 + 4]);
#pragma unroll
            for (int nb = 0; nb < 8; nb++) {
                uint32_t b0 = __float_as_uint(Vs[(kb * 8 + tid4)     * PVP + nb * 8 + gid]);
                uint32_t b1 = __float_as_uint(Vs[(kb * 8 + tid4 + 4) * PVP + nb * 8 + gid]);
                mma_tf32(Oacc[nb][0], Oacc[nb][1], Oacc[nb][2], Oacc[nb][3],
                         pa0, pa1, pa2, pa3, b0, b1);
            }
        }

        // ---- store normalized P tile (each warp its own 16 rows) ----
        if (write_attn) {
            float* ag = attng + kt * 64;
            for (int i = lane; i < 256; i += 32) {
                int r = w * 16 + (i >> 4), c4 = i & 15;
                *(float4*)(ag + (size_t)r * SS + c4 * 4) = *(const float4*)&Ps[r * PP + c4 * 4];
            }
        }
        __syncthreads();   // protect Kt/Vs restage
    }

    // ---- out = O (already normalized) ----
    float* og = out + ((size_t)(b * SS + qt * QROWS)) * EE + h * DD;
#pragma unroll
    for (int nb = 0; nb < 8; nb++) {
        *(float2*)(og + (size_t)qr0       * EE + nb * 8 + 2 * tid4) =
            make_float2(Oacc[nb][0], Oacc[nb][1]);
        *(float2*)(og + (size_t)(qr0 + 8) * EE + nb * 8 + 2 * tid4) =
            make_float2(Oacc[nb][2], Oacc[nb][3]);
    }
}

static const size_t SHMEM_SUMS = (size_t)64 * PK * sizeof(float);                           // 17408
static const size_t SHMEM_MAIN = (size_t)64 * (PK + PVP + PP) * sizeof(float);              // 53248

static bool setup_once()
{
    cudaFuncSetAttribute(attn_sums, cudaFuncAttributeMaxDynamicSharedMemorySize,
                         (int)SHMEM_SUMS);
    cudaFuncSetAttribute(attn_main, cudaFuncAttributeMaxDynamicSharedMemorySize,
                         (int)SHMEM_MAIN);
    return true;
}

extern "C" void kernel_launch(void* const* d_in, const int* in_sizes, int n_in,
                              void* d_out, int out_size)
{
    static bool ready = setup_once();
    (void)ready;

    const float* q = (const float*)d_in[0];
    const float* k = (const float*)d_in[1];
    const float* v = (const float*)d_in[2];
    float* out  = (float*)d_out;
    float* attn = out + OUT_ELEMS;

    const long long need = OUT_ELEMS + ATTN_ELEMS;
    const int write_attn = ((long long)out_size >= need) ? 1 : 0;

    dim3 grid(SS / QROWS, HH, BB);
    attn_sums<<<grid, 128, SHMEM_SUMS>>>(q, k);
    attn_main<<<grid, 128, SHMEM_MAIN>>>(q, k, v, out, attn, write_attn);
}